// round 6
// baseline (speedup 1.0000x reference)
#include <cuda_runtime.h>
#include <math_constants.h>
#include <cstdint>
#include <cstddef>

// Problem shape (fixed by the reference)
#define BB 64
#define TT 4096
#define DD 512

// Stage-A tiling
#define NWARP   8                 // warps per block
#define CHUNK   512               // t-rows per block
#define TPW     (CHUNK / NWARP)   // 64 t-rows per warp
#define NCHUNK  (TT / CHUNK)      // 8 chunks per batch row
#define NP      (NCHUNK * NWARP)  // 64 partials per batch row

// Device scratch (allocation-free contract: __device__ globals)
__device__ float g_k[BB * DD];                    // 128 KB  projected keys
__device__ float g_m[BB * NP];                    // per-partial running max
__device__ float g_s[BB * NP];                    // per-partial running sum
__device__ float g_ctx[(size_t)BB * NP * DD];     // 8 MB    per-partial context
__device__ int   g_mask_is_u8;                    // 1 => mask is 1-byte bool

// ---------------------------------------------------------------------------
// Mask dtype detection: if the first 65536 int32 words contain ANY value
// outside {0,1}, the buffer must be 1-byte bools (random 0/1 bytes make such
// words with overwhelming probability). 65536 words = 256 KB, valid for both
// interpretations (uint8 buffer is exactly 256 KB).
// ---------------------------------------------------------------------------
__global__ void mask_flag_init() { g_mask_is_u8 = 0; }

__global__ void mask_detect(const unsigned int* __restrict__ mw) {
    int i = blockIdx.x * blockDim.x + threadIdx.x;
    int found = 0;
    for (; i < 65536; i += gridDim.x * blockDim.x) {
        unsigned int v = mw[i];
        if (v > 1u) found = 1;
    }
    if (__syncthreads_or(found)) {
        if (threadIdx.x == 0) atomicOr(&g_mask_is_u8, 1);
    }
}

// ---------------------------------------------------------------------------
// Kernel 1: k[b,:] = query[b,:] @ W^T + bias   (W is [D,D] row-major)
// One block per batch row; q row in smem; each thread streams one W row.
// W (1 MB) is L2-resident across the 64 blocks.
// ---------------------------------------------------------------------------
__global__ void __launch_bounds__(DD) proj_kernel(
    const float* __restrict__ q, const float* __restrict__ W,
    const float* __restrict__ bias)
{
    __shared__ float qs[DD];
    const int b = blockIdx.x;
    const int d = threadIdx.x;
    qs[d] = q[b * DD + d];
    __syncthreads();

    const float4* wr = reinterpret_cast<const float4*>(W + (size_t)d * DD);
    float acc = bias[d];
#pragma unroll 8
    for (int j = 0; j < DD / 4; j++) {
        float4 wv = wr[j];
        acc = fmaf(qs[4 * j + 0], wv.x, acc);
        acc = fmaf(qs[4 * j + 1], wv.y, acc);
        acc = fmaf(qs[4 * j + 2], wv.z, acc);
        acc = fmaf(qs[4 * j + 3], wv.w, acc);
    }
    g_k[b * DD + d] = acc;
}

// ---------------------------------------------------------------------------
// Kernel 2: fused scores + online softmax + context accumulation.
// attend_to is read from HBM exactly once. Each warp handles 64 interleaved
// t-rows; lane owns d = j*128 + lane*4 (j=0..3) -> fully coalesced LDG.128.
// ---------------------------------------------------------------------------
__global__ void __launch_bounds__(256, 2) attn_pass(
    const float* __restrict__ A, const void* __restrict__ mask_raw)
{
    const int b    = blockIdx.x / NCHUNK;
    const int c    = blockIdx.x % NCHUNK;
    const int w    = threadIdx.x >> 5;
    const int lane = threadIdx.x & 31;

    const int u8 = g_mask_is_u8;
    const unsigned char* __restrict__ m8  = (const unsigned char*)mask_raw;
    const int*           __restrict__ m32 = (const int*)mask_raw;

    // Key slice for this lane's d-assignment
    float4 kk0, kk1, kk2, kk3;
    {
        const float* kp = &g_k[b * DD + lane * 4];
        kk0 = *(const float4*)(kp);
        kk1 = *(const float4*)(kp + 128);
        kk2 = *(const float4*)(kp + 256);
        kk3 = *(const float4*)(kp + 384);
    }

    float m = -CUDART_INF_F, s = 0.f;
    float4 cx0 = make_float4(0.f, 0.f, 0.f, 0.f);
    float4 cx1 = cx0, cx2 = cx0, cx3 = cx0;

    const float* Ab = A + (size_t)b * TT * DD;

    int t = c * CHUNK + w;
    // prefetch t0
    float4 a0, a1, a2, a3;
    {
        const float* p = Ab + (size_t)t * DD + lane * 4;
        a0 = *(const float4*)(p);
        a1 = *(const float4*)(p + 128);
        a2 = *(const float4*)(p + 256);
        a3 = *(const float4*)(p + 384);
    }
    unsigned char mk;
    if (u8) mk = m8[t * BB + b];
    else    mk = (unsigned char)(m32[t * BB + b] != 0);

#pragma unroll 2
    for (int i = 0; i < TPW; i++) {
        // ---- prefetch next t (clamped so the last iteration stays in-bounds)
        const int tn = t + NWARP;
        const int tc = (tn < TT) ? tn : (TT - 1);
        const float* pn = Ab + (size_t)tc * DD + lane * 4;
        float4 n0 = *(const float4*)(pn);
        float4 n1 = *(const float4*)(pn + 128);
        float4 n2 = *(const float4*)(pn + 256);
        float4 n3 = *(const float4*)(pn + 384);
        unsigned char mkn;
        if (u8) mkn = m8[tc * BB + b];
        else    mkn = (unsigned char)(m32[tc * BB + b] != 0);

        // ---- dot(a[t,:], k[:]) : 4 independent partials, then tree-combine
        float d0 = a0.x * kk0.x; d0 = fmaf(a0.y, kk0.y, d0);
        d0 = fmaf(a0.z, kk0.z, d0); d0 = fmaf(a0.w, kk0.w, d0);
        float d1 = a1.x * kk1.x; d1 = fmaf(a1.y, kk1.y, d1);
        d1 = fmaf(a1.z, kk1.z, d1); d1 = fmaf(a1.w, kk1.w, d1);
        float d2 = a2.x * kk2.x; d2 = fmaf(a2.y, kk2.y, d2);
        d2 = fmaf(a2.z, kk2.z, d2); d2 = fmaf(a2.w, kk2.w, d2);
        float d3 = a3.x * kk3.x; d3 = fmaf(a3.y, kk3.y, d3);
        d3 = fmaf(a3.z, kk3.z, d3); d3 = fmaf(a3.w, kk3.w, d3);
        float v = (d0 + d1) + (d2 + d3);

        // butterfly reduce -> all lanes hold the full dot
        v += __shfl_xor_sync(0xffffffffu, v, 16);
        v += __shfl_xor_sync(0xffffffffu, v, 8);
        v += __shfl_xor_sync(0xffffffffu, v, 4);
        v += __shfl_xor_sync(0xffffffffu, v, 2);
        v += __shfl_xor_sync(0xffffffffu, v, 1);

        const float sc = mk ? -CUDART_INF_F : v;

        // ---- online softmax update
        if (sc > m) {                       // false when sc == -inf
            const float f = __expf(m - sc); // m == -inf -> f = 0 (zeros state)
            s *= f;
            cx0.x *= f; cx0.y *= f; cx0.z *= f; cx0.w *= f;
            cx1.x *= f; cx1.y *= f; cx1.z *= f; cx1.w *= f;
            cx2.x *= f; cx2.y *= f; cx2.z *= f; cx2.w *= f;
            cx3.x *= f; cx3.y *= f; cx3.z *= f; cx3.w *= f;
            m = sc;
        }
        const float p = (sc == -CUDART_INF_F) ? 0.f : __expf(sc - m);
        s += p;
        cx0.x = fmaf(p, a0.x, cx0.x); cx0.y = fmaf(p, a0.y, cx0.y);
        cx0.z = fmaf(p, a0.z, cx0.z); cx0.w = fmaf(p, a0.w, cx0.w);
        cx1.x = fmaf(p, a1.x, cx1.x); cx1.y = fmaf(p, a1.y, cx1.y);
        cx1.z = fmaf(p, a1.z, cx1.z); cx1.w = fmaf(p, a1.w, cx1.w);
        cx2.x = fmaf(p, a2.x, cx2.x); cx2.y = fmaf(p, a2.y, cx2.y);
        cx2.z = fmaf(p, a2.z, cx2.z); cx2.w = fmaf(p, a2.w, cx2.w);
        cx3.x = fmaf(p, a3.x, cx3.x); cx3.y = fmaf(p, a3.y, cx3.y);
        cx3.z = fmaf(p, a3.z, cx3.z); cx3.w = fmaf(p, a3.w, cx3.w);

        a0 = n0; a1 = n1; a2 = n2; a3 = n3; mk = mkn; t = tn;
    }

    // ---- write per-warp partial
    const int pi = b * NP + c * NWARP + w;
    if (lane == 0) { g_m[pi] = m; g_s[pi] = s; }
    float* cp = &g_ctx[(size_t)pi * DD + lane * 4];
    *(float4*)(cp)       = cx0;
    *(float4*)(cp + 128) = cx1;
    *(float4*)(cp + 256) = cx2;
    *(float4*)(cp + 384) = cx3;
}

// ---------------------------------------------------------------------------
// Kernel 3: split-KV combine. One block per batch row; thread d-slice merges
// the 64 partials with max-rescaling, then normalizes.
// ---------------------------------------------------------------------------
__global__ void __launch_bounds__(128) combine_kernel(float* __restrict__ out)
{
    const int b   = blockIdx.x;
    const int tid = threadIdx.x;

    float mstar = -CUDART_INF_F;
#pragma unroll
    for (int i = 0; i < NP; i++)
        mstar = fmaxf(mstar, g_m[b * NP + i]);

    float denom = 0.f;
    float ax = 0.f, ay = 0.f, az = 0.f, aw = 0.f;
    for (int i = 0; i < NP; i++) {
        const float e = __expf(g_m[b * NP + i] - mstar);
        denom = fmaf(g_s[b * NP + i], e, denom);
        const float4 cv =
            *(const float4*)&g_ctx[(size_t)(b * NP + i) * DD + tid * 4];
        ax = fmaf(cv.x, e, ax);
        ay = fmaf(cv.y, e, ay);
        az = fmaf(cv.z, e, az);
        aw = fmaf(cv.w, e, aw);
    }
    const float inv = 1.f / denom;
    float4 o = make_float4(ax * inv, ay * inv, az * inv, aw * inv);
    *(float4*)&out[b * DD + tid * 4] = o;
}

// ---------------------------------------------------------------------------
// Launch contract
// Inputs (metadata order): query[B,D] f32, attend_to[B,T,D] f32,
//                          mask[T,B] bool, W[D,D] f32, b[D] f32
// Output: context[B,1,D] f32
// ---------------------------------------------------------------------------
extern "C" void kernel_launch(void* const* d_in, const int* in_sizes, int n_in,
                              void* d_out, int out_size)
{
    (void)in_sizes; (void)n_in; (void)out_size;
    const float* q    = (const float*)d_in[0];
    const float* A    = (const float*)d_in[1];
    const void*  mask = d_in[2];
    const float* W    = (const float*)d_in[3];
    const float* bias = (const float*)d_in[4];
    float* out = (float*)d_out;

    mask_flag_init<<<1, 1>>>();
    mask_detect<<<64, 256>>>((const unsigned int*)mask);
    proj_kernel<<<BB, DD>>>(q, W, bias);
    attn_pass<<<BB * NCHUNK, 256>>>(A, mask);
    combine_kernel<<<BB, 128>>>(out);
}

// round 7
// speedup vs baseline: 1.0799x; 1.0799x over previous
#include <cuda_runtime.h>
#include <math_constants.h>
#include <cstdint>
#include <cstddef>

// Problem shape (fixed by the reference)
#define BB 64
#define TT 4096
#define DD 512

// Stage-A tiling
#define NWARP   8                 // warps per block
#define CHUNK   256               // t-rows per block
#define TPW     (CHUNK / NWARP)   // 32 t-rows per warp
#define NCHUNK  (TT / CHUNK)      // 16 chunks per batch row

// Device scratch (allocation-free contract: __device__ globals)
__device__ float        g_k[BB * DD];                       // projected keys
__device__ float        g_m[BB * NCHUNK];                   // block-partial max
__device__ float        g_s[BB * NCHUNK];                   // block-partial sum
__device__ float        g_ctx[(size_t)BB * NCHUNK * DD];    // 2 MB block-partial ctx
__device__ unsigned int g_cnt[BB];                          // per-batch arrival count
__device__ int          g_mask_is_u8;                       // 1 => mask is 1-byte bool

// ---------------------------------------------------------------------------
// Setup kernel: one block per batch row.
//  - projects k[b,:] = q[b,:] @ W^T + bias (W stays L2-resident)
//  - block 0 additionally detects the mask dtype (any int32 word > 1 =>
//    the buffer must be 1-byte bools)
//  - resets this batch's combine counter (needed for every graph replay)
// ---------------------------------------------------------------------------
__global__ void __launch_bounds__(DD) setup_kernel(
    const float* __restrict__ q, const float* __restrict__ W,
    const float* __restrict__ bias, const unsigned int* __restrict__ mw)
{
    __shared__ float qs[DD];
    const int b = blockIdx.x;
    const int d = threadIdx.x;

    if (d == 0) g_cnt[b] = 0u;

    qs[d] = q[b * DD + d];
    __syncthreads();

    const float4* wr = reinterpret_cast<const float4*>(W + (size_t)d * DD);
    float acc = bias[d];
#pragma unroll 8
    for (int j = 0; j < DD / 4; j++) {
        float4 wv = wr[j];
        acc = fmaf(qs[4 * j + 0], wv.x, acc);
        acc = fmaf(qs[4 * j + 1], wv.y, acc);
        acc = fmaf(qs[4 * j + 2], wv.z, acc);
        acc = fmaf(qs[4 * j + 3], wv.w, acc);
    }
    g_k[b * DD + d] = acc;

    if (b == 0) {
        // 65536 words = 256 KB: valid for both u8 (exactly TT*BB bytes) and i32.
        int found = 0;
        for (int i = d; i < 65536; i += DD) {
            if (mw[i] > 1u) found = 1;
        }
        const int any = __syncthreads_or(found);
        if (d == 0) g_mask_is_u8 = any;
    }
}

// ---------------------------------------------------------------------------
// Fused attention pass: online-softmax flash pass over a 256-row chunk,
// block-level partial merge in smem, then last-arriving block per batch
// performs the final split-KV combine and writes the output row.
// attend_to is read from HBM exactly once.
// ---------------------------------------------------------------------------
__global__ void __launch_bounds__(256) attn_pass(
    const float* __restrict__ A, const void* __restrict__ mask_raw,
    float* __restrict__ out)
{
    const int b    = blockIdx.x >> 4;     // NCHUNK = 16
    const int c    = blockIdx.x & 15;
    const int tid  = threadIdx.x;
    const int w    = tid >> 5;
    const int lane = tid & 31;

    const int u8 = g_mask_is_u8;
    const unsigned char* __restrict__ m8  = (const unsigned char*)mask_raw;
    const int*           __restrict__ m32 = (const int*)mask_raw;

    // Key slice for this lane's d-assignment (d = j*128 + lane*4)
    float4 kk0, kk1, kk2, kk3;
    {
        const float* kp = &g_k[b * DD + lane * 4];
        kk0 = *(const float4*)(kp);
        kk1 = *(const float4*)(kp + 128);
        kk2 = *(const float4*)(kp + 256);
        kk3 = *(const float4*)(kp + 384);
    }

    float m = -CUDART_INF_F, s = 0.f;
    float4 cx0 = make_float4(0.f, 0.f, 0.f, 0.f);
    float4 cx1 = cx0, cx2 = cx0, cx3 = cx0;

    const float* Ab = A + (size_t)b * TT * DD;

    int t = c * CHUNK + w;
    // prefetch t0
    float4 a0, a1, a2, a3;
    {
        const float* p = Ab + (size_t)t * DD + lane * 4;
        a0 = *(const float4*)(p);
        a1 = *(const float4*)(p + 128);
        a2 = *(const float4*)(p + 256);
        a3 = *(const float4*)(p + 384);
    }
    unsigned char mk;
    if (u8) mk = m8[t * BB + b];
    else    mk = (unsigned char)(m32[t * BB + b] != 0);

#pragma unroll 2
    for (int i = 0; i < TPW; i++) {
        // ---- prefetch next t (clamped so the last iteration stays in-bounds)
        const int tn = t + NWARP;
        const int tc = (tn < TT) ? tn : (TT - 1);
        const float* pn = Ab + (size_t)tc * DD + lane * 4;
        float4 n0 = *(const float4*)(pn);
        float4 n1 = *(const float4*)(pn + 128);
        float4 n2 = *(const float4*)(pn + 256);
        float4 n3 = *(const float4*)(pn + 384);
        unsigned char mkn;
        if (u8) mkn = m8[tc * BB + b];
        else    mkn = (unsigned char)(m32[tc * BB + b] != 0);

        // ---- dot(a[t,:], k[:]) : 4 independent partials, then tree-combine
        float d0 = a0.x * kk0.x; d0 = fmaf(a0.y, kk0.y, d0);
        d0 = fmaf(a0.z, kk0.z, d0); d0 = fmaf(a0.w, kk0.w, d0);
        float d1 = a1.x * kk1.x; d1 = fmaf(a1.y, kk1.y, d1);
        d1 = fmaf(a1.z, kk1.z, d1); d1 = fmaf(a1.w, kk1.w, d1);
        float d2 = a2.x * kk2.x; d2 = fmaf(a2.y, kk2.y, d2);
        d2 = fmaf(a2.z, kk2.z, d2); d2 = fmaf(a2.w, kk2.w, d2);
        float d3 = a3.x * kk3.x; d3 = fmaf(a3.y, kk3.y, d3);
        d3 = fmaf(a3.z, kk3.z, d3); d3 = fmaf(a3.w, kk3.w, d3);
        float v = (d0 + d1) + (d2 + d3);

        // butterfly reduce -> all lanes hold the full dot
        v += __shfl_xor_sync(0xffffffffu, v, 16);
        v += __shfl_xor_sync(0xffffffffu, v, 8);
        v += __shfl_xor_sync(0xffffffffu, v, 4);
        v += __shfl_xor_sync(0xffffffffu, v, 2);
        v += __shfl_xor_sync(0xffffffffu, v, 1);

        const float sc = mk ? -CUDART_INF_F : v;

        // ---- online softmax update
        if (sc > m) {                       // false when sc == -inf
            const float f = __expf(m - sc); // m == -inf -> f = 0 (zeros state)
            s *= f;
            cx0.x *= f; cx0.y *= f; cx0.z *= f; cx0.w *= f;
            cx1.x *= f; cx1.y *= f; cx1.z *= f; cx1.w *= f;
            cx2.x *= f; cx2.y *= f; cx2.z *= f; cx2.w *= f;
            cx3.x *= f; cx3.y *= f; cx3.z *= f; cx3.w *= f;
            m = sc;
        }
        const float p = (sc == -CUDART_INF_F) ? 0.f : __expf(sc - m);
        s += p;
        cx0.x = fmaf(p, a0.x, cx0.x); cx0.y = fmaf(p, a0.y, cx0.y);
        cx0.z = fmaf(p, a0.z, cx0.z); cx0.w = fmaf(p, a0.w, cx0.w);
        cx1.x = fmaf(p, a1.x, cx1.x); cx1.y = fmaf(p, a1.y, cx1.y);
        cx1.z = fmaf(p, a1.z, cx1.z); cx1.w = fmaf(p, a1.w, cx1.w);
        cx2.x = fmaf(p, a2.x, cx2.x); cx2.y = fmaf(p, a2.y, cx2.y);
        cx2.z = fmaf(p, a2.z, cx2.z); cx2.w = fmaf(p, a2.w, cx2.w);
        cx3.x = fmaf(p, a3.x, cx3.x); cx3.y = fmaf(p, a3.y, cx3.y);
        cx3.z = fmaf(p, a3.z, cx3.z); cx3.w = fmaf(p, a3.w, cx3.w);

        a0 = n0; a1 = n1; a2 = n2; a3 = n3; mk = mkn; t = tn;
    }

    // ======================= block-level partial merge ======================
    __shared__ float sm_m[NWARP];
    __shared__ float sm_s[NWARP];
    __shared__ float sm_ctx[NWARP][DD];
    __shared__ unsigned int s_old;

    if (lane == 0) { sm_m[w] = m; sm_s[w] = s; }
    {
        float* cp = &sm_ctx[w][lane * 4];
        *(float4*)(cp)       = cx0;
        *(float4*)(cp + 128) = cx1;
        *(float4*)(cp + 256) = cx2;
        *(float4*)(cp + 384) = cx3;
    }
    __syncthreads();

    float mstar = -CUDART_INF_F;
#pragma unroll
    for (int ww = 0; ww < NWARP; ww++) mstar = fmaxf(mstar, sm_m[ww]);

    float denom = 0.f, acc0 = 0.f, acc1 = 0.f;
#pragma unroll
    for (int ww = 0; ww < NWARP; ww++) {
        const float mw2 = sm_m[ww];
        const float ew = (mw2 == -CUDART_INF_F) ? 0.f : __expf(mw2 - mstar);
        denom = fmaf(sm_s[ww], ew, denom);
        acc0  = fmaf(sm_ctx[ww][tid],       ew, acc0);
        acc1  = fmaf(sm_ctx[ww][tid + 256], ew, acc1);
    }

    const int pi = b * NCHUNK + c;
    if (tid == 0) { g_m[pi] = mstar; g_s[pi] = denom; }
    g_ctx[(size_t)pi * DD + tid]       = acc0;
    g_ctx[(size_t)pi * DD + tid + 256] = acc1;

    // ================== last-block-per-batch final combine ==================
    __threadfence();           // release partials before signaling arrival
    __syncthreads();
    if (tid == 0) s_old = atomicAdd(&g_cnt[b], 1u);
    __syncthreads();
    if (s_old != NCHUNK - 1) return;

    __threadfence();           // acquire all other blocks' partials

    float mg = -CUDART_INF_F;
#pragma unroll
    for (int i = 0; i < NCHUNK; i++) mg = fmaxf(mg, g_m[b * NCHUNK + i]);

    float den = 0.f, o0 = 0.f, o1 = 0.f;
#pragma unroll 4
    for (int i = 0; i < NCHUNK; i++) {
        const float mi = g_m[b * NCHUNK + i];
        const float e  = (mi == -CUDART_INF_F) ? 0.f : __expf(mi - mg);
        den = fmaf(g_s[b * NCHUNK + i], e, den);
        const float* cp = &g_ctx[(size_t)(b * NCHUNK + i) * DD];
        o0 = fmaf(cp[tid],       e, o0);
        o1 = fmaf(cp[tid + 256], e, o1);
    }
    const float inv = 1.f / den;
    out[b * DD + tid]       = o0 * inv;
    out[b * DD + tid + 256] = o1 * inv;
}

// ---------------------------------------------------------------------------
// Launch contract
// Inputs (metadata order): query[B,D] f32, attend_to[B,T,D] f32,
//                          mask[T,B] bool, W[D,D] f32, b[D] f32
// Output: context[B,1,D] f32
// ---------------------------------------------------------------------------
extern "C" void kernel_launch(void* const* d_in, const int* in_sizes, int n_in,
                              void* d_out, int out_size)
{
    (void)in_sizes; (void)n_in; (void)out_size;
    const float* q    = (const float*)d_in[0];
    const float* A    = (const float*)d_in[1];
    const void*  mask = d_in[2];
    const float* W    = (const float*)d_in[3];
    const float* bias = (const float*)d_in[4];
    float* out = (float*)d_out;

    setup_kernel<<<BB, DD>>>(q, W, bias, (const unsigned int*)mask);
    attn_pass<<<BB * NCHUNK, 256>>>(A, mask, out);
}

// round 8
// speedup vs baseline: 1.1971x; 1.1085x over previous
#include <cuda_runtime.h>
#include <math_constants.h>
#include <cstdint>
#include <cstddef>

// Problem shape (fixed by the reference)
#define BB 64
#define TT 4096
#define DD 512
#define ROWS (BB * TT)          // 262144 flattened (b,t) rows
#define NWARP 8
#define MAXG 512                // upper bound on persistent grid size

// Device scratch (allocation-free contract: __device__ globals)
__device__ float        g_k[BB * DD];                    // projected keys
__device__ float        g_pm[MAXG * 2];                  // per-(block,seg) max
__device__ float        g_ps[MAXG * 2];                  // per-(block,seg) sum
__device__ float        g_pctx[(size_t)MAXG * 2 * DD];   // per-(block,seg) ctx (2 MB)
__device__ unsigned int g_cnt[BB];                       // per-batch arrival count

// ---------------------------------------------------------------------------
// Setup: k[b,:] = q[b,:] @ W^T + bias (W stays L2-resident) + counter reset.
// ---------------------------------------------------------------------------
__global__ void __launch_bounds__(DD) setup_kernel(
    const float* __restrict__ q, const float* __restrict__ W,
    const float* __restrict__ bias)
{
    __shared__ float qs[DD];
    const int b = blockIdx.x;
    const int d = threadIdx.x;
    if (b == 0 && d < BB) g_cnt[d] = 0u;   // reset for every graph replay
    qs[d] = q[b * DD + d];
    __syncthreads();

    const float4* wr = reinterpret_cast<const float4*>(W + (size_t)d * DD);
    float acc = bias[d];
#pragma unroll 8
    for (int jj = 0; jj < DD / 4; jj++) {
        float4 wv = wr[jj];
        acc = fmaf(qs[4 * jj + 0], wv.x, acc);
        acc = fmaf(qs[4 * jj + 1], wv.y, acc);
        acc = fmaf(qs[4 * jj + 2], wv.z, acc);
        acc = fmaf(qs[4 * jj + 3], wv.w, acc);
    }
    g_k[b * DD + d] = acc;
}

// ---------------------------------------------------------------------------
// Persistent fused attention. Block j owns flattened rows [S, S+Len) with
// Len = ROWS/G (+1). A slice crosses at most one batch boundary; warps keep
// online-softmax state, flush per-segment into smem at the boundary, the
// block merges 8 warps -> <=2 global partials, and the last-arriving block
// per batch performs the split-KV combine. attend_to is read from HBM once.
// ---------------------------------------------------------------------------
__global__ void __launch_bounds__(256, 3) attn_pass(
    const float* __restrict__ A, const void* __restrict__ mask_raw,
    float* __restrict__ out)
{
    const int j    = blockIdx.x;
    const int G    = gridDim.x;
    const int tid  = threadIdx.x;
    const int w    = tid >> 5;
    const int lane = tid & 31;

    const int L    = ROWS / G;
    const int rem  = ROWS % G;
    const int S    = (j < rem) ? j * (L + 1) : rem * (L + 1) + (j - rem) * L;
    const int Len  = (j < rem) ? (L + 1) : L;
    const int Eblk = S + Len;
    const int bF   = S >> 12;               // block's first batch
    const int bL   = (Eblk - 1) >> 12;      // block's last batch
    const int has2 = (bL != bF);

    // ---- per-block mask dtype self-detection (256-word sample) ----
    const unsigned int* mwords = (const unsigned int*)mask_raw;
    const int u8 = __syncthreads_or((int)(mwords[(j * 256 + tid) & 65535] > 1u));
    const unsigned char* __restrict__ m8  = (const unsigned char*)mask_raw;
    const int*           __restrict__ m32 = (const int*)mask_raw;

    __shared__ float sm_m[2][NWARP];
    __shared__ float sm_s[2][NWARP];
    __shared__ float sm_ctx[2][NWARP][DD];
    __shared__ unsigned int s_o0, s_o1;

    // warp-local zeroing of this warp's slots (both segments) — race-free
#pragma unroll
    for (int sg = 0; sg < 2; sg++) {
        if (lane == 0) { sm_m[sg][w] = -CUDART_INF_F; sm_s[sg][w] = 0.f; }
        for (int i = lane; i < DD / 4; i += 32)
            ((float4*)sm_ctx[sg][w])[i] = make_float4(0.f, 0.f, 0.f, 0.f);
    }

    // ---- flash loop over this warp's rows: r = S + w, step 8 ----
    int r    = S + w;
    int bcur = r >> 12;

    float4 kk0, kk1, kk2, kk3;
    {
        const float* kp = &g_k[bcur * DD + lane * 4];
        kk0 = *(const float4*)(kp);
        kk1 = *(const float4*)(kp + 128);
        kk2 = *(const float4*)(kp + 256);
        kk3 = *(const float4*)(kp + 384);
    }

    float m = -CUDART_INF_F, s = 0.f;
    float4 cx0 = make_float4(0.f, 0.f, 0.f, 0.f);
    float4 cx1 = cx0, cx2 = cx0, cx3 = cx0;

    // prefetch first row
    float4 a0, a1, a2, a3;
    {
        const float* p = A + (size_t)r * DD + lane * 4;
        a0 = *(const float4*)(p);
        a1 = *(const float4*)(p + 128);
        a2 = *(const float4*)(p + 256);
        a3 = *(const float4*)(p + 384);
    }
    unsigned char mk;
    {
        const int t = r & 4095, bb = r >> 12;
        if (u8) mk = m8[t * BB + bb];
        else    mk = (unsigned char)(m32[t * BB + bb] != 0);
    }

    for (;;) {
        // ---- prefetch next row (clamped to the global end; always valid A)
        const int rn = r + NWARP;
        const int rc = (rn < ROWS) ? rn : (ROWS - 1);
        const float* pn = A + (size_t)rc * DD + lane * 4;
        float4 n0 = *(const float4*)(pn);
        float4 n1 = *(const float4*)(pn + 128);
        float4 n2 = *(const float4*)(pn + 256);
        float4 n3 = *(const float4*)(pn + 384);
        unsigned char mkn;
        {
            const int t = rc & 4095, bb = rc >> 12;
            if (u8) mkn = m8[t * BB + bb];
            else    mkn = (unsigned char)(m32[t * BB + bb] != 0);
        }

        // ---- dot(a[r,:], k[:])
        float d0 = a0.x * kk0.x; d0 = fmaf(a0.y, kk0.y, d0);
        d0 = fmaf(a0.z, kk0.z, d0); d0 = fmaf(a0.w, kk0.w, d0);
        float d1 = a1.x * kk1.x; d1 = fmaf(a1.y, kk1.y, d1);
        d1 = fmaf(a1.z, kk1.z, d1); d1 = fmaf(a1.w, kk1.w, d1);
        float d2 = a2.x * kk2.x; d2 = fmaf(a2.y, kk2.y, d2);
        d2 = fmaf(a2.z, kk2.z, d2); d2 = fmaf(a2.w, kk2.w, d2);
        float d3 = a3.x * kk3.x; d3 = fmaf(a3.y, kk3.y, d3);
        d3 = fmaf(a3.z, kk3.z, d3); d3 = fmaf(a3.w, kk3.w, d3);
        float v = (d0 + d1) + (d2 + d3);

        v += __shfl_xor_sync(0xffffffffu, v, 16);
        v += __shfl_xor_sync(0xffffffffu, v, 8);
        v += __shfl_xor_sync(0xffffffffu, v, 4);
        v += __shfl_xor_sync(0xffffffffu, v, 2);
        v += __shfl_xor_sync(0xffffffffu, v, 1);

        const float sc = mk ? -CUDART_INF_F : v;

        // ---- online softmax update
        if (sc > m) {
            const float f = __expf(m - sc);   // m == -inf -> f = 0
            s *= f;
            cx0.x *= f; cx0.y *= f; cx0.z *= f; cx0.w *= f;
            cx1.x *= f; cx1.y *= f; cx1.z *= f; cx1.w *= f;
            cx2.x *= f; cx2.y *= f; cx2.z *= f; cx2.w *= f;
            cx3.x *= f; cx3.y *= f; cx3.z *= f; cx3.w *= f;
            m = sc;
        }
        const float p = (sc == -CUDART_INF_F) ? 0.f : __expf(sc - m);
        s += p;
        cx0.x = fmaf(p, a0.x, cx0.x); cx0.y = fmaf(p, a0.y, cx0.y);
        cx0.z = fmaf(p, a0.z, cx0.z); cx0.w = fmaf(p, a0.w, cx0.w);
        cx1.x = fmaf(p, a1.x, cx1.x); cx1.y = fmaf(p, a1.y, cx1.y);
        cx1.z = fmaf(p, a1.z, cx1.z); cx1.w = fmaf(p, a1.w, cx1.w);
        cx2.x = fmaf(p, a2.x, cx2.x); cx2.y = fmaf(p, a2.y, cx2.y);
        cx2.z = fmaf(p, a2.z, cx2.z); cx2.w = fmaf(p, a2.w, cx2.w);
        cx3.x = fmaf(p, a3.x, cx3.x); cx3.y = fmaf(p, a3.y, cx3.y);
        cx3.z = fmaf(p, a3.z, cx3.z); cx3.w = fmaf(p, a3.w, cx3.w);

        r = rn;
        if (r >= Eblk) break;

        const int bnew = r >> 12;
        if (bnew != bcur) {                 // warp-uniform, executes <= once
            const int sg = (bcur == bF) ? 0 : 1;
            if (lane == 0) { sm_m[sg][w] = m; sm_s[sg][w] = s; }
            float* cp = &sm_ctx[sg][w][lane * 4];
            *(float4*)(cp)       = cx0;
            *(float4*)(cp + 128) = cx1;
            *(float4*)(cp + 256) = cx2;
            *(float4*)(cp + 384) = cx3;
            m = -CUDART_INF_F; s = 0.f;
            cx0 = make_float4(0.f, 0.f, 0.f, 0.f);
            cx1 = cx0; cx2 = cx0; cx3 = cx0;
            const float* kp = &g_k[bnew * DD + lane * 4];
            kk0 = *(const float4*)(kp);
            kk1 = *(const float4*)(kp + 128);
            kk2 = *(const float4*)(kp + 256);
            kk3 = *(const float4*)(kp + 384);
            bcur = bnew;
        }
        a0 = n0; a1 = n1; a2 = n2; a3 = n3; mk = mkn;
    }
    // final flush of the current segment
    {
        const int sg = (bcur == bF) ? 0 : 1;
        if (lane == 0) { sm_m[sg][w] = m; sm_s[sg][w] = s; }
        float* cp = &sm_ctx[sg][w][lane * 4];
        *(float4*)(cp)       = cx0;
        *(float4*)(cp + 128) = cx1;
        *(float4*)(cp + 256) = cx2;
        *(float4*)(cp + 384) = cx3;
    }
    __syncthreads();

    // ---- block merge: 8 warp partials -> 1 global partial per segment ----
#pragma unroll
    for (int sg = 0; sg < 2; sg++) {
        if (sg == 1 && !has2) break;
        float mstar = -CUDART_INF_F;
#pragma unroll
        for (int ww = 0; ww < NWARP; ww++) mstar = fmaxf(mstar, sm_m[sg][ww]);
        float den = 0.f, acc0 = 0.f, acc1 = 0.f;
#pragma unroll
        for (int ww = 0; ww < NWARP; ww++) {
            const float mw2 = sm_m[sg][ww];
            const float ew = (mw2 == -CUDART_INF_F) ? 0.f : __expf(mw2 - mstar);
            den  = fmaf(sm_s[sg][ww], ew, den);
            acc0 = fmaf(sm_ctx[sg][ww][tid],       ew, acc0);
            acc1 = fmaf(sm_ctx[sg][ww][tid + 256], ew, acc1);
        }
        const int slot = j * 2 + sg;
        if (tid == 0) { g_pm[slot] = mstar; g_ps[slot] = den; }
        g_pctx[(size_t)slot * DD + tid]       = acc0;
        g_pctx[(size_t)slot * DD + tid + 256] = acc1;
    }

    // ---- arrive; last block per batch combines ----
    __threadfence();
    __syncthreads();
    if (tid == 0) {
        s_o0 = atomicAdd(&g_cnt[bF], 1u);
        if (has2) s_o1 = atomicAdd(&g_cnt[bL], 1u);
    }
    __syncthreads();

    const int t1 = rem * (L + 1);
    // j_of(r): block index owning flattened row r
    // S_of(jj): first row of block jj
#define J_OF(rr)  (((rr) < t1) ? (rr) / (L + 1) : rem + ((rr) - t1) / L)
#define S_OF(jj)  (((jj) < rem) ? (jj) * (L + 1) : t1 + ((jj) - rem) * L)

#pragma unroll
    for (int which = 0; which < 2; which++) {
        if (which == 1 && !has2) break;
        const int b    = (which == 0) ? bF : bL;
        const int jlo  = J_OF(b << 12);
        const int jhi  = J_OF(((b + 1) << 12) - 1);
        const unsigned int expect = (unsigned int)(jhi - jlo + 1);
        const unsigned int got = (which == 0) ? s_o0 : s_o1;
        if (got != expect - 1) continue;

        __threadfence();   // acquire all contributors' partials

        float mg = -CUDART_INF_F;
        for (int jj = jlo; jj <= jhi; jj++) {
            const int sg = ((S_OF(jj) >> 12) == b) ? 0 : 1;
            mg = fmaxf(mg, g_pm[jj * 2 + sg]);
        }
        float den = 0.f, o0 = 0.f, o1 = 0.f;
        for (int jj = jlo; jj <= jhi; jj++) {
            const int sg = ((S_OF(jj) >> 12) == b) ? 0 : 1;
            const int sl = jj * 2 + sg;
            const float mi = g_pm[sl];
            const float e  = (mi == -CUDART_INF_F) ? 0.f : __expf(mi - mg);
            den = fmaf(g_ps[sl], e, den);
            o0  = fmaf(g_pctx[(size_t)sl * DD + tid],       e, o0);
            o1  = fmaf(g_pctx[(size_t)sl * DD + tid + 256], e, o1);
        }
        const float inv = 1.f / den;
        out[b * DD + tid]       = o0 * inv;
        out[b * DD + tid + 256] = o1 * inv;
    }
#undef J_OF
#undef S_OF
}

// ---------------------------------------------------------------------------
// Launch contract
// Inputs (metadata order): query[B,D] f32, attend_to[B,T,D] f32,
//                          mask[T,B] bool, W[D,D] f32, b[D] f32
// Output: context[B,1,D] f32
// ---------------------------------------------------------------------------
extern "C" void kernel_launch(void* const* d_in, const int* in_sizes, int n_in,
                              void* d_out, int out_size)
{
    (void)in_sizes; (void)n_in; (void)out_size;
    const float* q    = (const float*)d_in[0];
    const float* A    = (const float*)d_in[1];
    const void*  mask = d_in[2];
    const float* W    = (const float*)d_in[3];
    const float* bias = (const float*)d_in[4];
    float* out = (float*)d_out;

    int dev = 0;
    cudaGetDevice(&dev);
    int sms = 148;
    cudaDeviceGetAttribute(&sms, cudaDevAttrMultiProcessorCount, dev);
    int grid = sms * 3;            // exactly one resident wave (occ 3 blocks/SM)
    if (grid > MAXG) grid = MAXG;

    setup_kernel<<<BB, DD>>>(q, W, bias);
    attn_pass<<<grid, 256>>>(A, mask, out);
}

// round 11
// speedup vs baseline: 1.3431x; 1.1220x over previous
#include <cuda_runtime.h>
#include <math_constants.h>
#include <cstdint>
#include <cstddef>

// Problem shape (fixed by the reference)
#define BB 64
#define TT 4096
#define DD 512
#define ROWS (BB * TT)          // 262144 flattened (b,t) rows
#define NWARP 8
#define MAXG 512                // upper bound on persistent grid size

// Device scratch (allocation-free contract: __device__ globals)
__device__ float        g_k[BB * DD];                    // projected keys
__device__ float        g_pm[MAXG * 2];                  // per-(block,seg) max
__device__ float        g_ps[MAXG * 2];                  // per-(block,seg) sum
__device__ float        g_pctx[(size_t)MAXG * 2 * DD];   // per-(block,seg) ctx (2 MB)
__device__ unsigned int g_cnt[BB];                       // per-batch arrival count

// ---------------------------------------------------------------------------
// Setup kernel: key projection, warp-per-output-row (coalesced W reads).
// Block j (64 blocks, 8 warps): warp w owns output row d = j*8 + w and keeps
// its W row slice in registers; loops over the 64 batches with the q row
// staged in smem; butterfly dot-reduce. Also resets combine counters.
// ---------------------------------------------------------------------------
__global__ void __launch_bounds__(256) setup_kernel(
    const float* __restrict__ q, const float* __restrict__ W,
    const float* __restrict__ bias)
{
    __shared__ float qs[DD];
    const int j    = blockIdx.x;
    const int tid  = threadIdx.x;
    const int w    = tid >> 5;
    const int lane = tid & 31;

    if (j == 0 && tid < BB) g_cnt[tid] = 0u;   // reset for every graph replay

    const int d = j * NWARP + w;               // this warp's output row
    const float* wr = W + (size_t)d * DD + lane * 4;
    const float4 w0 = *(const float4*)(wr);
    const float4 w1 = *(const float4*)(wr + 128);
    const float4 w2 = *(const float4*)(wr + 256);
    const float4 w3 = *(const float4*)(wr + 384);
    const float bv = bias[d];

    for (int b = 0; b < BB; b++) {
        __syncthreads();
        qs[tid]       = q[b * DD + tid];
        qs[tid + 256] = q[b * DD + tid + 256];
        __syncthreads();
        const float4 q0 = *(const float4*)&qs[lane * 4];
        const float4 q1 = *(const float4*)&qs[lane * 4 + 128];
        const float4 q2 = *(const float4*)&qs[lane * 4 + 256];
        const float4 q3 = *(const float4*)&qs[lane * 4 + 384];
        float v = w0.x * q0.x;
        v = fmaf(w0.y, q0.y, v); v = fmaf(w0.z, q0.z, v); v = fmaf(w0.w, q0.w, v);
        v = fmaf(w1.x, q1.x, v); v = fmaf(w1.y, q1.y, v);
        v = fmaf(w1.z, q1.z, v); v = fmaf(w1.w, q1.w, v);
        v = fmaf(w2.x, q2.x, v); v = fmaf(w2.y, q2.y, v);
        v = fmaf(w2.z, q2.z, v); v = fmaf(w2.w, q2.w, v);
        v = fmaf(w3.x, q3.x, v); v = fmaf(w3.y, q3.y, v);
        v = fmaf(w3.z, q3.z, v); v = fmaf(w3.w, q3.w, v);
        v += __shfl_xor_sync(0xffffffffu, v, 16);
        v += __shfl_xor_sync(0xffffffffu, v, 8);
        v += __shfl_xor_sync(0xffffffffu, v, 4);
        v += __shfl_xor_sync(0xffffffffu, v, 2);
        v += __shfl_xor_sync(0xffffffffu, v, 1);
        if (lane == 0) g_k[b * DD + d] = v + bv;
    }
}

// ---------------------------------------------------------------------------
// Persistent fused attention. Block j owns flattened rows [S, S+Len) with
// Len = ROWS/G (+1); slices cross at most one batch boundary. Warps keep
// online-softmax state, flush per-segment into smem, block merges 8 warps ->
// <=2 global partials, last-arriving block per batch does the split-KV
// combine. attend_to is read from HBM exactly once. No spin-waits anywhere:
// the kernel cannot deadlock regardless of block residency.
// ---------------------------------------------------------------------------
__global__ void __launch_bounds__(256, 3) attn_pass(
    const float* __restrict__ A, const void* __restrict__ mask_raw,
    float* __restrict__ out)
{
    const int j    = blockIdx.x;
    const int G    = gridDim.x;
    const int tid  = threadIdx.x;
    const int w    = tid >> 5;
    const int lane = tid & 31;

    const int L    = ROWS / G;
    const int rem  = ROWS % G;
    const int S    = (j < rem) ? j * (L + 1) : rem * (L + 1) + (j - rem) * L;
    const int Len  = (j < rem) ? (L + 1) : L;
    const int Eblk = S + Len;
    const int bF   = S >> 12;               // block's first batch
    const int bL   = (Eblk - 1) >> 12;      // block's last batch
    const int has2 = (bL != bF);

    // ---- per-block mask dtype self-detection (256-word sample):
    // random bool bytes make an int32 word >1 with p=7/8 per word.
    const unsigned int* mwords = (const unsigned int*)mask_raw;
    const int u8 = __syncthreads_or((int)(mwords[(j * 256 + tid) & 65535] > 1u));
    const unsigned char* __restrict__ m8  = (const unsigned char*)mask_raw;
    const int*           __restrict__ m32 = (const int*)mask_raw;

    __shared__ float sm_m[2][NWARP];
    __shared__ float sm_s[2][NWARP];
    __shared__ float sm_ctx[2][NWARP][DD];
    __shared__ unsigned int s_o0, s_o1;

    // warp-local zeroing of this warp's partial slots (both segments)
#pragma unroll
    for (int sg = 0; sg < 2; sg++) {
        if (lane == 0) { sm_m[sg][w] = -CUDART_INF_F; sm_s[sg][w] = 0.f; }
        for (int i = lane; i < DD / 4; i += 32)
            ((float4*)sm_ctx[sg][w])[i] = make_float4(0.f, 0.f, 0.f, 0.f);
    }

    int r    = S + w;
    int bcur = bF;

    float4 kk0, kk1, kk2, kk3;
    {
        const float* kp = &g_k[bcur * DD + lane * 4];
        kk0 = *(const float4*)(kp);
        kk1 = *(const float4*)(kp + 128);
        kk2 = *(const float4*)(kp + 256);
        kk3 = *(const float4*)(kp + 384);
    }

    float m = -CUDART_INF_F, s = 0.f;
    float4 cx0 = make_float4(0.f, 0.f, 0.f, 0.f);
    float4 cx1 = cx0, cx2 = cx0, cx3 = cx0;

    float4 a0, a1, a2, a3, n0, n1, n2, n3;
    unsigned char mk, mkn;

#define PREFETCH(D0, D1, D2, D3, DM, RC)                                      \
    {   const float* _p = A + (size_t)(RC) * DD + lane * 4;                   \
        D0 = *(const float4*)(_p);                                            \
        D1 = *(const float4*)(_p + 128);                                      \
        D2 = *(const float4*)(_p + 256);                                      \
        D3 = *(const float4*)(_p + 384);                                      \
        const int _t = (RC) & 4095, _b = (RC) >> 12;                          \
        if (u8) DM = m8[_t * BB + _b];                                        \
        else    DM = (unsigned char)(m32[_t * BB + _b] != 0); }

#define PROCESS(A0, A1, A2, A3, MK)                                           \
    {   float d0 = A0.x * kk0.x; d0 = fmaf(A0.y, kk0.y, d0);                  \
        d0 = fmaf(A0.z, kk0.z, d0); d0 = fmaf(A0.w, kk0.w, d0);               \
        float d1 = A1.x * kk1.x; d1 = fmaf(A1.y, kk1.y, d1);                  \
        d1 = fmaf(A1.z, kk1.z, d1); d1 = fmaf(A1.w, kk1.w, d1);               \
        float d2 = A2.x * kk2.x; d2 = fmaf(A2.y, kk2.y, d2);                  \
        d2 = fmaf(A2.z, kk2.z, d2); d2 = fmaf(A2.w, kk2.w, d2);               \
        float d3 = A3.x * kk3.x; d3 = fmaf(A3.y, kk3.y, d3);                  \
        d3 = fmaf(A3.z, kk3.z, d3); d3 = fmaf(A3.w, kk3.w, d3);               \
        float v = (d0 + d1) + (d2 + d3);                                      \
        v += __shfl_xor_sync(0xffffffffu, v, 16);                             \
        v += __shfl_xor_sync(0xffffffffu, v, 8);                              \
        v += __shfl_xor_sync(0xffffffffu, v, 4);                              \
        v += __shfl_xor_sync(0xffffffffu, v, 2);                              \
        v += __shfl_xor_sync(0xffffffffu, v, 1);                              \
        const float sc = (MK) ? -CUDART_INF_F : v;                            \
        if (sc > m) {                                                         \
            const float f = __expf(m - sc);                                   \
            s *= f;                                                           \
            cx0.x *= f; cx0.y *= f; cx0.z *= f; cx0.w *= f;                   \
            cx1.x *= f; cx1.y *= f; cx1.z *= f; cx1.w *= f;                   \
            cx2.x *= f; cx2.y *= f; cx2.z *= f; cx2.w *= f;                   \
            cx3.x *= f; cx3.y *= f; cx3.z *= f; cx3.w *= f;                   \
            m = sc;                                                           \
        }                                                                     \
        const float p = (sc == -CUDART_INF_F) ? 0.f : __expf(sc - m);         \
        s += p;                                                               \
        cx0.x = fmaf(p, A0.x, cx0.x); cx0.y = fmaf(p, A0.y, cx0.y);           \
        cx0.z = fmaf(p, A0.z, cx0.z); cx0.w = fmaf(p, A0.w, cx0.w);           \
        cx1.x = fmaf(p, A1.x, cx1.x); cx1.y = fmaf(p, A1.y, cx1.y);           \
        cx1.z = fmaf(p, A1.z, cx1.z); cx1.w = fmaf(p, A1.w, cx1.w);           \
        cx2.x = fmaf(p, A2.x, cx2.x); cx2.y = fmaf(p, A2.y, cx2.y);           \
        cx2.z = fmaf(p, A2.z, cx2.z); cx2.w = fmaf(p, A2.w, cx2.w);           \
        cx3.x = fmaf(p, A3.x, cx3.x); cx3.y = fmaf(p, A3.y, cx3.y);           \
        cx3.z = fmaf(p, A3.z, cx3.z); cx3.w = fmaf(p, A3.w, cx3.w); }

#define FLUSH()                                                               \
    {   const int _sg = (bcur == bF) ? 0 : 1;                                 \
        if (lane == 0) { sm_m[_sg][w] = m; sm_s[_sg][w] = s; }                \
        float* _cp = &sm_ctx[_sg][w][lane * 4];                               \
        *(float4*)(_cp)       = cx0;                                          \
        *(float4*)(_cp + 128) = cx1;                                          \
        *(float4*)(_cp + 256) = cx2;                                          \
        *(float4*)(_cp + 384) = cx3; }

#define BOUNDARY()                                                            \
    {   const int _bn = r >> 12;                                              \
        if (_bn != bcur) {                                                    \
            FLUSH();                                                          \
            m = -CUDART_INF_F; s = 0.f;                                       \
            cx0 = make_float4(0.f, 0.f, 0.f, 0.f);                            \
            cx1 = cx0; cx2 = cx0; cx3 = cx0;                                  \
            const float* _kp = &g_k[_bn * DD + lane * 4];                     \
            kk0 = *(const float4*)(_kp);                                      \
            kk1 = *(const float4*)(_kp + 128);                                \
            kk2 = *(const float4*)(_kp + 256);                                \
            kk3 = *(const float4*)(_kp + 384);                                \
            bcur = _bn; } }

    PREFETCH(a0, a1, a2, a3, mk, r);
    for (;;) {
        // half 1: process a (row r), prefetch r+8 into n
        int rn = r + NWARP;
        int rc = (rn < ROWS) ? rn : (ROWS - 1);
        PREFETCH(n0, n1, n2, n3, mkn, rc);
        PROCESS(a0, a1, a2, a3, mk);
        r = rn;
        if (r >= Eblk) break;
        BOUNDARY();
        // half 2: process n (row r), prefetch r+8 into a
        rn = r + NWARP;
        rc = (rn < ROWS) ? rn : (ROWS - 1);
        PREFETCH(a0, a1, a2, a3, mk, rc);
        PROCESS(n0, n1, n2, n3, mkn);
        r = rn;
        if (r >= Eblk) break;
        BOUNDARY();
    }
    FLUSH();
    __syncthreads();

    // ---- block merge: 8 warp partials -> 1 global partial per segment ----
#pragma unroll
    for (int sg = 0; sg < 2; sg++) {
        if (sg == 1 && !has2) break;
        float mstar = -CUDART_INF_F;
#pragma unroll
        for (int ww = 0; ww < NWARP; ww++) mstar = fmaxf(mstar, sm_m[sg][ww]);
        float den = 0.f, acc0 = 0.f, acc1 = 0.f;
#pragma unroll
        for (int ww = 0; ww < NWARP; ww++) {
            const float mw2 = sm_m[sg][ww];
            const float ew = (mw2 == -CUDART_INF_F) ? 0.f : __expf(mw2 - mstar);
            den  = fmaf(sm_s[sg][ww], ew, den);
            acc0 = fmaf(sm_ctx[sg][ww][tid],       ew, acc0);
            acc1 = fmaf(sm_ctx[sg][ww][tid + 256], ew, acc1);
        }
        const int slot = j * 2 + sg;
        if (tid == 0) { g_pm[slot] = mstar; g_ps[slot] = den; }
        g_pctx[(size_t)slot * DD + tid]       = acc0;
        g_pctx[(size_t)slot * DD + tid + 256] = acc1;
    }

    // ---- arrive; last block per batch combines ----
    __threadfence();
    __syncthreads();
    if (tid == 0) {
        s_o0 = atomicAdd(&g_cnt[bF], 1u);
        if (has2) s_o1 = atomicAdd(&g_cnt[bL], 1u);
    }
    __syncthreads();

    const int t1 = rem * (L + 1);
#define J_OF(rr)  (((rr) < t1) ? (rr) / (L + 1) : rem + ((rr) - t1) / L)
#define S_OF(jj)  (((jj) < rem) ? (jj) * (L + 1) : t1 + ((jj) - rem) * L)

#pragma unroll
    for (int which = 0; which < 2; which++) {
        if (which == 1 && !has2) break;
        const int b   = (which == 0) ? bF : bL;
        const int jlo = J_OF(b << 12);
        const int jhi = J_OF(((b + 1) << 12) - 1);
        const unsigned int expect = (unsigned int)(jhi - jlo + 1);
        const unsigned int got = (which == 0) ? s_o0 : s_o1;
        if (got != expect - 1) continue;

        __threadfence();   // acquire all contributors' partials

        float mg = -CUDART_INF_F;
        for (int jj = jlo; jj <= jhi; jj++) {
            const int sg = ((S_OF(jj) >> 12) == b) ? 0 : 1;
            mg = fmaxf(mg, g_pm[jj * 2 + sg]);
        }
        float den = 0.f, o0 = 0.f, o1 = 0.f;
        for (int jj = jlo; jj <= jhi; jj++) {
            const int sg = ((S_OF(jj) >> 12) == b) ? 0 : 1;
            const int sl = jj * 2 + sg;
            const float mi = g_pm[sl];
            const float e  = (mi == -CUDART_INF_F) ? 0.f : __expf(mi - mg);
            den = fmaf(g_ps[sl], e, den);
            o0  = fmaf(g_pctx[(size_t)sl * DD + tid],       e, o0);
            o1  = fmaf(g_pctx[(size_t)sl * DD + tid + 256], e, o1);
        }
        const float inv = 1.f / den;
        out[b * DD + tid]       = o0 * inv;
        out[b * DD + tid + 256] = o1 * inv;
    }
#undef J_OF
#undef S_OF
}

// ---------------------------------------------------------------------------
// Launch contract
// Inputs (metadata order): query[B,D] f32, attend_to[B,T,D] f32,
//                          mask[T,B] bool, W[D,D] f32, b[D] f32
// Output: context[B,1,D] f32
// ---------------------------------------------------------------------------
extern "C" void kernel_launch(void* const* d_in, const int* in_sizes, int n_in,
                              void* d_out, int out_size)
{
    (void)in_sizes; (void)n_in; (void)out_size;
    const float* q    = (const float*)d_in[0];
    const float* A    = (const float*)d_in[1];
    const void*  mask = d_in[2];
    const float* W    = (const float*)d_in[3];
    const float* bias = (const float*)d_in[4];
    float* out = (float*)d_out;

    int sms = 0;
    if (cudaDeviceGetAttribute(&sms, cudaDevAttrMultiProcessorCount, 0)
            != cudaSuccess || sms <= 0)
        sms = 152;                 // GB300 default (R8 profile: grid 456 = 152*3)
    int grid = sms * 3;            // one fully-resident wave (3 blocks/SM)
    if (grid > MAXG) grid = MAXG;

    setup_kernel<<<BB, 256>>>(q, W, bias);
    attn_pass<<<grid, 256>>>(A, mask, out);
}